// round 14
// baseline (speedup 1.0000x reference)
#include <cuda_runtime.h>
#include <cuda_fp16.h>
#include <cstdint>

#define CC   128
#define BB   8
#define EE   8
#define NG   4
#define HWPIX 4096
#define IMG  524288   // 128*64*64
#define YSZ  4194304  // 8*128*64*64
#define NRP  32       // row-pairs per image
#define NBLK 256      // b x row-pair units for scratch indexing

__device__ float g_x0[BB * CC];
__device__ float g_w[NG * BB * EE];

// Pre-converted fp16 weights (swizzled 16KB chunk images)
__device__ uint32_t g_wc_f16[EE * 18 * 4096];
__device__ uint32_t g_wp_f16[EE * 2 * 4096];
// per-expert v staging: [e][b*32+rp][co][px]
__device__ float g_scr[(size_t)EE * NBLK * 16384];

// ---------------------------------------------------------------------------
__global__ void mean_kernel(const float* __restrict__ x) {
    int bc = blockIdx.x;
    const float4* p = (const float4*)(x + (size_t)bc * HWPIX);
    float s = 0.f;
    for (int i = threadIdx.x; i < 1024; i += 256) { float4 v = p[i]; s += (v.x + v.y) + (v.z + v.w); }
    for (int o = 16; o; o >>= 1) s += __shfl_xor_sync(0xffffffffu, s, o);
    __shared__ float sm[8];
    if ((threadIdx.x & 31) == 0) sm[threadIdx.x >> 5] = s;
    __syncthreads();
    if (threadIdx.x < 8) {
        float v = sm[threadIdx.x];
        for (int o = 4; o; o >>= 1) v += __shfl_xor_sync(0xffu, v, o);
        if (threadIdx.x == 0) g_x0[bc] = v * (1.0f / 4096.0f);
    }
}

__global__ void gate_kernel(const float* __restrict__ g1, const float* __restrict__ g2,
                            const float* __restrict__ g3, const float* __restrict__ g4,
                            float* __restrict__ loss_out) {
    int lane = threadIdx.x;
    int g = lane >> 3, b = lane & 7;
    const float* G = (g == 0) ? g1 : (g == 1) ? g2 : (g == 2) ? g3 : g4;
    const float* x0 = &g_x0[b * CC];
    float lg[8];
#pragma unroll
    for (int e = 0; e < 8; e++) lg[e] = 0.f;
    for (int c = 0; c < CC; c++) {
        float xv = x0[c];
#pragma unroll
        for (int e = 0; e < 8; e++) lg[e] += xv * G[c * 8 + e];
    }
    float m = lg[0];
#pragma unroll
    for (int e = 1; e < 8; e++) m = fmaxf(m, lg[e]);
    float p[8], sum = 0.f;
#pragma unroll
    for (int e = 0; e < 8; e++) { p[e] = expf(lg[e] - m); sum += p[e]; }
    float inv = 1.f / sum;
#pragma unroll
    for (int e = 0; e < 8; e++) p[e] *= inv;
    int i1 = 0;
#pragma unroll
    for (int e = 1; e < 8; e++) if (p[e] > p[i1]) i1 = e;
    int i2 = (i1 == 0) ? 1 : 0;
#pragma unroll
    for (int e = 0; e < 8; e++) { if (e == i1 || e == i2) continue; if (p[e] > p[i2]) i2 = e; }
    float m2 = fmaxf(p[i1], p[i2]);
    float e1 = expf(p[i1] - m2), e2 = expf(p[i2] - m2);
    float winv = 1.f / (e1 + e2);
    float* wrow = &g_w[(g * 8 + b) * 8];
#pragma unroll
    for (int e = 0; e < 8; e++) wrow[e] = 0.f;
    wrow[i1] = e1 * winv;
    wrow[i2] = e2 * winv;
    float u[8];
#pragma unroll
    for (int e = 0; e < 8; e++) {
        u[e] = p[e];
        for (int o = 1; o < 8; o <<= 1) u[e] += __shfl_xor_sync(0xffffffffu, u[e], o);
    }
    __shared__ float sl[4];
    if (b == 0) {
        float mu = 0.f;
#pragma unroll
        for (int e = 0; e < 8; e++) mu += u[e];
        mu *= (1.0f / 8.0f);
        float var = 0.f;
#pragma unroll
        for (int e = 0; e < 8; e++) { float d = u[e] - mu; var += d * d; }
        var *= (1.0f / 7.0f);
        sl[g] = var / (mu * mu + 1e-10f);
    }
    __syncwarp();
    if (lane == 0) loss_out[0] = sl[0] + sl[1] + sl[2] + sl[3];
}

__device__ __forceinline__ uint32_t packh2(float a, float b) {
    __half2 h; h.x = __float2half_rn(a); h.y = __float2half_rn(b);
    return *(uint32_t*)&h;
}

__global__ void prep_wc(const float* __restrict__ Wc_all) {
    int e = blockIdx.x / 18, cc = blockIdx.x % 18;
    int j = cc >> 1, h = cc & 1;
    const float* Wc = Wc_all + (size_t)e * (CC * 1152);
    uint32_t* oh = g_wc_f16 + (size_t)blockIdx.x * 4096;
#pragma unroll 4
    for (int idx = threadIdx.x; idx < 4096; idx += 256) {
        int r = idx >> 6, cop = idx & 63;
        int co = cop * 2, ci = h * 64 + r;
        float v0 = __ldg(Wc + (size_t)co * 1152 + ci * 9 + j);
        float v1 = __ldg(Wc + (size_t)(co + 1) * 1152 + ci * 9 + j);
        uint32_t woff = (r * 256 + ((co * 2) ^ ((r & 7) << 4))) >> 2;
        oh[woff] = packh2(v0, v1);
    }
}

__global__ void prep_wp(const float* __restrict__ Wp_all) {
    int e = blockIdx.x >> 1, h = blockIdx.x & 1;
    const float* Wp = Wp_all + (size_t)e * 16384;
    uint32_t* oh = g_wp_f16 + (size_t)blockIdx.x * 4096;
#pragma unroll 4
    for (int idx = threadIdx.x; idx < 4096; idx += 256) {
        int r = idx >> 6, cop = idx & 63;
        int co = cop * 2, ci = h * 64 + r;
        float v0 = __ldg(Wp + (size_t)co * 128 + ci);
        float v1 = __ldg(Wp + (size_t)(co + 1) * 128 + ci);
        uint32_t woff = (r * 256 + ((co * 2) ^ ((r & 7) << 4))) >> 2;
        oh[woff] = packh2(v0, v1);
    }
}

// ---------------------------------------------------------------------------
// Main kernel (round 14): expert-parallel. Grid 2048 = (b,e) pair x row-pair.
// Each block: ONE expert, ONE 128px strip. R13 body, expert loop removed.
// ---------------------------------------------------------------------------

#define SXH   0                    // x fp16: 264 rows x 256B = 67584
#define WOFF  67584                // 4 x 16KB buffers (multi-use)
#define SPARTB 133120              // 2 x 128 floats
#define SSCB  134144               // 128 floats
#define SMEM_BYTES 134656

__device__ __forceinline__ void ldsm4(uint32_t a, uint32_t* r) {
    asm volatile("ldmatrix.sync.aligned.m8n8.x4.shared.b16 {%0,%1,%2,%3}, [%4];"
                 : "=r"(r[0]), "=r"(r[1]), "=r"(r[2]), "=r"(r[3]) : "r"(a));
}
__device__ __forceinline__ void ldsm4t(uint32_t a, uint32_t* r) {
    asm volatile("ldmatrix.sync.aligned.m8n8.x4.trans.shared.b16 {%0,%1,%2,%3}, [%4];"
                 : "=r"(r[0]), "=r"(r[1]), "=r"(r[2]), "=r"(r[3]) : "r"(a));
}
__device__ __forceinline__ void mma_fp(float* d, const uint32_t* a,
                                       uint32_t b0, uint32_t b1) {
    asm volatile(
        "mma.sync.aligned.m16n8k16.row.col.f32.f16.f16.f32 "
        "{%0,%1,%2,%3},{%4,%5,%6,%7},{%8,%9},{%0,%1,%2,%3};"
        : "+f"(d[0]), "+f"(d[1]), "+f"(d[2]), "+f"(d[3])
        : "r"(a[0]), "r"(a[1]), "r"(a[2]), "r"(a[3]), "r"(b0), "r"(b1));
}
__device__ __forceinline__ uint32_t amat_addr(uint32_t base, int R0, int ci0, int lane) {
    int sel = lane >> 3;
    int r = R0 + (lane & 7) + ((sel & 1) << 3);
    int cb = (ci0 + ((sel >> 1) << 3)) * 2;
    return base + r * 256 + (cb ^ ((r & 7) << 4));
}
__device__ __forceinline__ void cp16s(uint32_t dst, const void* src) {
    asm volatile("cp.async.ca.shared.global [%0], [%1], 16;" :: "r"(dst), "l"(src));
}
#define CP_COMMIT() asm volatile("cp.async.commit_group;")
#define CP_WAIT2()  asm volatile("cp.async.wait_group 2;")
#define CP_WAIT1()  asm volatile("cp.async.wait_group 1;")
#define CP_WAIT0()  asm volatile("cp.async.wait_group 0;")

__global__ void __launch_bounds__(256, 1)
moe_main(const float* __restrict__ x,
         const float* __restrict__ bc_all, const float* __restrict__ bp_all) {
    extern __shared__ char smem[];
    const uint32_t sb = (uint32_t)__cvta_generic_to_shared(smem);
    float* spart = (float*)(smem + SPARTB);
    float* ssc   = (float*)(smem + SSCB);

    const int tid  = threadIdx.x;
    const int lane = tid & 31;
    const int warp = tid >> 5;
    const int wq = warp >> 1;          // px group of 32
    const int wh = warp & 1;           // co half
    const int pair = blockIdx.x >> 5;  // 0..63 = b*8+e
    const int rp   = blockIdx.x & 31;
    const int b = pair >> 3, e = pair & 7;
    const int row0 = rp * 2;
    const int gq = lane >> 2, t4 = lane & 3;

    // selected? (all threads read same 4 words - broadcast)
    float we0 = g_w[(0 * 8 + b) * 8 + e];
    float we1 = g_w[(1 * 8 + b) * 8 + e];
    float we2 = g_w[(2 * 8 + b) * 8 + e];
    float we3 = g_w[(3 * 8 + b) * 8 + e];
    if (we0 == 0.f && we1 == 0.f && we2 == 0.f && we3 == 0.f) return;

    auto loadW = [&](int cc, int bf) {
        const uint32_t* src = g_wc_f16 + (size_t)(e * 18 + cc) * 4096;
#pragma unroll
        for (int k = 0; k < 4; ++k) {
            int i = tid + k * 256;
            cp16s(sb + WOFF + bf * 16384 + i * 16, src + i * 4);
        }
        CP_COMMIT();
    };
    loadW(0, 0);   // overlap W streaming with x-strip load
    loadW(1, 1);
    loadW(2, 2);

    // ---- x strip (4 halo rows, 66 cols, 128 ci), fp16 swizzled ----
    {
        const float* xb = x + (size_t)b * IMG;
        for (int it = 0; it < 64; ++it) {
            int rid = warp + it * 8;
            int gry = rid >> 7, ci = rid & 127;
            int gr = row0 - 1 + gry;
#pragma unroll
            for (int cl = 0; cl < 3; ++cl) {
                int c = lane + cl * 32;
                if (cl == 2 && lane >= 2) break;
                int gc = c - 1;
                float v = 0.f;
                if ((unsigned)gr < 64u && (unsigned)gc < 64u)
                    v = xb[ci * HWPIX + gr * 64 + gc];
                int R = gry * 66 + c;
                uint32_t off = R * 256 + ((ci * 2) ^ ((R & 7) << 4));
                *(__half*)(smem + SXH + off) = __float2half_rn(v);
            }
        }
    }

    float acc[2][8][4];
#pragma unroll
    for (int pm = 0; pm < 2; ++pm)
#pragma unroll
        for (int f = 0; f < 8; ++f)
#pragma unroll
            for (int i = 0; i < 4; ++i) acc[pm][f][i] = 0.f;

    // ---- GEMM1: 18 chunks, quad-buffered, fragment-pipelined inner ----
    for (int cc = 0; cc < 18; ++cc) {
        if (cc < 16) { CP_WAIT2(); } else if (cc == 16) { CP_WAIT1(); } else { CP_WAIT0(); }
        __syncthreads();
        if (cc + 3 < 18) loadW(cc + 3, (cc + 3) & 3);

        const int j = cc >> 1;
        const int ky = j / 3, kx = j - 3 * (j / 3);
        const int h = cc & 1;
        const uint32_t whb = sb + WOFF + (cc & 3) * 16384;
        const int Rb0 = ((wq * 32) >> 6) * 66 + ((wq * 32) & 63) + ky * 66 + kx;
        const int Rb1 = (((wq * 32 + 16) >> 6)) * 66 + ((wq * 32 + 16) & 63) + ky * 66 + kx;

        uint32_t ah[2][2][4], bh[2][4][4];
        ldsm4(amat_addr(sb + SXH, Rb0, h * 64, lane), ah[0][0]);
        ldsm4(amat_addr(sb + SXH, Rb1, h * 64, lane), ah[0][1]);
#pragma unroll
        for (int nn = 0; nn < 4; ++nn)
            ldsm4t(amat_addr(whb, 0, wh * 64 + nn * 16, lane), bh[0][nn]);
#pragma unroll
        for (int ks = 0; ks < 4; ++ks) {
            const int cur = ks & 1, nst = cur ^ 1;
            if (ks < 3) {
                const int ci0 = h * 64 + (ks + 1) * 16;
                ldsm4(amat_addr(sb + SXH, Rb0, ci0, lane), ah[nst][0]);
                ldsm4(amat_addr(sb + SXH, Rb1, ci0, lane), ah[nst][1]);
#pragma unroll
                for (int nn = 0; nn < 4; ++nn)
                    ldsm4t(amat_addr(whb, (ks + 1) * 16, wh * 64 + nn * 16, lane), bh[nst][nn]);
            }
#pragma unroll
            for (int nn = 0; nn < 4; ++nn)
#pragma unroll
                for (int pm = 0; pm < 2; ++pm) {
                    mma_fp(acc[pm][nn * 2], ah[cur][pm], bh[cur][nn][0], bh[cur][nn][1]);
                    mma_fp(acc[pm][nn * 2 + 1], ah[cur][pm], bh[cur][nn][2], bh[cur][nn][3]);
                }
        }
    }
    __syncthreads();   // all buffers free

    // prefetch both W_proj half-images into buffers 2,3
    {
        const uint32_t* pH = g_wp_f16 + (size_t)e * 8192;
#pragma unroll
        for (int k = 0; k < 8; ++k) {
            int i = tid + k * 256;
            cp16s(sb + WOFF + 32768 + i * 16, pH + i * 4);
        }
        CP_COMMIT();
    }

    // ---- bias + per-pixel sum of squares ----
#pragma unroll
    for (int pm = 0; pm < 2; ++pm) {
        float sa = 0.f, sb2 = 0.f;
#pragma unroll
        for (int f = 0; f < 8; ++f) {
            int co = wh * 64 + f * 8 + t4 * 2;
            float bc0 = __ldg(&bc_all[e * CC + co]);
            float bc1 = __ldg(&bc_all[e * CC + co + 1]);
            acc[pm][f][0] += bc0; acc[pm][f][1] += bc1;
            acc[pm][f][2] += bc0; acc[pm][f][3] += bc1;
            sa = fmaf(acc[pm][f][0], acc[pm][f][0], sa);
            sa = fmaf(acc[pm][f][1], acc[pm][f][1], sa);
            sb2 = fmaf(acc[pm][f][2], acc[pm][f][2], sb2);
            sb2 = fmaf(acc[pm][f][3], acc[pm][f][3], sb2);
        }
        sa += __shfl_xor_sync(0xffffffffu, sa, 1);
        sa += __shfl_xor_sync(0xffffffffu, sa, 2);
        sb2 += __shfl_xor_sync(0xffffffffu, sb2, 1);
        sb2 += __shfl_xor_sync(0xffffffffu, sb2, 2);
        if (t4 == 0) {
            int pxa = wq * 32 + pm * 16 + gq;
            spart[wh * 128 + pxa] = sa;
            spart[wh * 128 + pxa + 8] = sb2;
        }
    }
    __syncthreads();
    if (tid < 128) {
        float sn = spart[tid] + spart[128 + tid];
        ssc[tid] = sn / (1.f + sn) / (sqrtf(sn) + 1e-8f);
    }
    __syncthreads();

    // ---- scale + stage u into buffers 0,1 (128 px rows x 256B, swizzled) ----
#pragma unroll
    for (int pm = 0; pm < 2; ++pm) {
        int pxa = wq * 32 + pm * 16 + gq;
        float s0 = ssc[pxa], s1 = ssc[pxa + 8];
#pragma unroll
        for (int f = 0; f < 8; ++f) {
            int cb = (wh * 64 + f * 8 + t4 * 2) * 2;
            uint32_t w0 = packh2(acc[pm][f][0] * s0, acc[pm][f][1] * s0);
            uint32_t o0 = pxa * 256 + (cb ^ ((pxa & 7) << 4));
            *(uint32_t*)(smem + WOFF + o0) = w0;
            uint32_t w1 = packh2(acc[pm][f][2] * s1, acc[pm][f][3] * s1);
            int px2 = pxa + 8;
            uint32_t o1 = px2 * 256 + (cb ^ ((px2 & 7) << 4));
            *(uint32_t*)(smem + WOFF + o1) = w1;
        }
    }
    CP_WAIT0();
    __syncthreads();

    // ---- GEMM2: K=128, fragment-pipelined (u in bufs 0-1, Wp in bufs 2-3) ----
#pragma unroll
    for (int pm = 0; pm < 2; ++pm)
#pragma unroll
        for (int f = 0; f < 8; ++f)
#pragma unroll
            for (int i = 0; i < 4; ++i) acc[pm][f][i] = 0.f;
    {
        uint32_t ah[2][2][4], bh[2][4][4];
        auto loadF2 = [&](int ks, int st) {
            int R0 = wq * 32, R1 = R0 + 16;
            ldsm4(amat_addr(sb + WOFF, R0, ks * 16, lane), ah[st][0]);
            ldsm4(amat_addr(sb + WOFF, R1, ks * 16, lane), ah[st][1]);
            uint32_t wpb = sb + WOFF + 32768 + (ks >> 2) * 16384;
            int kr = (ks & 3) * 16;
#pragma unroll
            for (int nn = 0; nn < 4; ++nn)
                ldsm4t(amat_addr(wpb, kr, wh * 64 + nn * 16, lane), bh[st][nn]);
        };
        loadF2(0, 0);
#pragma unroll
        for (int ks = 0; ks < 8; ++ks) {
            const int cur = ks & 1, nst = cur ^ 1;
            if (ks < 7) loadF2(ks + 1, nst);
#pragma unroll
            for (int nn = 0; nn < 4; ++nn)
#pragma unroll
                for (int pm = 0; pm < 2; ++pm) {
                    mma_fp(acc[pm][nn * 2], ah[cur][pm], bh[cur][nn][0], bh[cur][nn][1]);
                    mma_fp(acc[pm][nn * 2 + 1], ah[cur][pm], bh[cur][nn][2], bh[cur][nn][3]);
                }
        }
    }
    __syncthreads();   // done reading u/Wp; region reusable for staging

    // ---- v = acc + bp -> scratch (staged, coalesced float4 writes) ----
    float* stg = (float*)(smem + WOFF);   // [64 co][132]
    const int sblk = b * NRP + rp;
    for (int r = 0; r < 2; ++r) {
        if (wh == r) {
#pragma unroll
            for (int pm = 0; pm < 2; ++pm) {
                int pxa = wq * 32 + pm * 16 + gq;
#pragma unroll
                for (int f = 0; f < 8; ++f) {
                    int cl = f * 8 + t4 * 2;
                    float bp0 = __ldg(&bp_all[e * CC + r * 64 + cl]);
                    float bp1 = __ldg(&bp_all[e * CC + r * 64 + cl + 1]);
                    stg[cl * 132 + pxa]           = acc[pm][f][0] + bp0;
                    stg[(cl + 1) * 132 + pxa]     = acc[pm][f][1] + bp1;
                    stg[cl * 132 + pxa + 8]       = acc[pm][f][2] + bp0;
                    stg[(cl + 1) * 132 + pxa + 8] = acc[pm][f][3] + bp1;
                }
            }
        }
        __syncthreads();
        float* dst = g_scr + (size_t)(e * NBLK + sblk) * 16384 + r * 64 * 128;
#pragma unroll
        for (int k = 0; k < 8; ++k) {
            int i = tid + k * 256;
            int cl = i >> 5, p4 = (i & 31) * 4;
            float4 v = *(float4*)&stg[cl * 132 + p4];
            *(float4*)&dst[cl * 128 + p4] = v;
        }
        __syncthreads();
    }
}

// ---------------------------------------------------------------------------
// Combine kernel: y_g = sum_e w_ge * v_e. Grid 256 = b*32+rp, 256 threads.
// ---------------------------------------------------------------------------
__global__ void __launch_bounds__(256)
combine_kernel(float* __restrict__ out) {
    __shared__ float swg[32];
    const int tid = threadIdx.x;
    const int blk = blockIdx.x;
    const int b = blk >> 5, rp = blk & 31;
    const int row0 = rp * 2;
    if (tid < 32) {
        int g = tid >> 3, e = tid & 7;
        swg[tid] = g_w[(g * 8 + b) * 8 + e];
    }
    __syncthreads();
#pragma unroll 1
    for (int k = 0; k < 16; ++k) {
        int i = tid + k * 256;
        int co = i >> 5, p4 = (i & 31) * 4;
        float4 y0 = {0, 0, 0, 0}, y1 = y0, y2 = y0, y3 = y0;
#pragma unroll
        for (int e = 0; e < EE; ++e) {
            float a0 = swg[e], a1 = swg[8 + e], a2 = swg[16 + e], a3 = swg[24 + e];
            if (a0 == 0.f && a1 == 0.f && a2 == 0.f && a3 == 0.f) continue;
            float4 v = *(const float4*)(g_scr + (size_t)(e * NBLK + blk) * 16384 + co * 128 + p4);
            y0.x += a0 * v.x; y0.y += a0 * v.y; y0.z += a0 * v.z; y0.w += a0 * v.w;
            y1.x += a1 * v.x; y1.y += a1 * v.y; y1.z += a1 * v.z; y1.w += a1 * v.w;
            y2.x += a2 * v.x; y2.y += a2 * v.y; y2.z += a2 * v.z; y2.w += a2 * v.w;
            y3.x += a3 * v.x; y3.y += a3 * v.y; y3.z += a3 * v.z; y3.w += a3 * v.w;
        }
        int r2 = p4 >> 6, col = p4 & 63;
        size_t gidx = (size_t)b * IMG + (size_t)co * HWPIX + (size_t)(row0 + r2) * 64 + col;
        *(float4*)(out + gidx) = y0;
        *(float4*)(out + YSZ + gidx) = y1;
        *(float4*)(out + 2 * YSZ + gidx) = y2;
        *(float4*)(out + 3 * YSZ + gidx) = y3;
    }
}

// ---------------------------------------------------------------------------
extern "C" void kernel_launch(void* const* d_in, const int* in_sizes, int n_in,
                              void* d_out, int out_size) {
    const float* x  = (const float*)d_in[0];
    const float* g1 = (const float*)d_in[1];
    const float* g2 = (const float*)d_in[2];
    const float* g3 = (const float*)d_in[3];
    const float* g4 = (const float*)d_in[4];
    const float* Wc = (const float*)d_in[5];
    const float* bc = (const float*)d_in[6];
    const float* Wp = (const float*)d_in[7];
    const float* bp = (const float*)d_in[8];
    float* out = (float*)d_out;

    cudaFuncSetAttribute(moe_main, cudaFuncAttributeMaxDynamicSharedMemorySize, SMEM_BYTES);

    mean_kernel<<<BB * CC, 256>>>(x);
    gate_kernel<<<1, 32>>>(g1, g2, g3, g4, out + (out_size - 1));
    prep_wc<<<EE * 18, 256>>>(Wc);
    prep_wp<<<EE * 2, 256>>>(Wp);
    moe_main<<<BB * EE * NRP, 256, SMEM_BYTES>>>(x, bc, bp);
    combine_kernel<<<NBLK, 256>>>(out);
}

// round 15
// speedup vs baseline: 1.0594x; 1.0594x over previous
#include <cuda_runtime.h>
#include <cuda_fp16.h>
#include <cstdint>

#define CC   128
#define BB   8
#define EE   8
#define NG   4
#define HWPIX 4096
#define IMG  524288   // 128*64*64
#define YSZ  4194304  // 8*128*64*64
#define NBLK 256      // 8 b x 32 row-pairs

__device__ float g_x0[BB * CC];
__device__ float g_w[NG * BB * EE];

// Pre-converted fp16 weights (swizzled 16KB chunk images)
__device__ uint32_t g_wc_f16[EE * 18 * 4096];
__device__ uint32_t g_wp_f16[EE * 2 * 4096];
// per-expert v staging: [e][blk][co][px]
__device__ float g_scr[(size_t)EE * NBLK * 16384];

// ---------------------------------------------------------------------------
__global__ void mean_kernel(const float* __restrict__ x) {
    int bc = blockIdx.x;
    const float4* p = (const float4*)(x + (size_t)bc * HWPIX);
    float s = 0.f;
    for (int i = threadIdx.x; i < 1024; i += 256) { float4 v = p[i]; s += (v.x + v.y) + (v.z + v.w); }
    for (int o = 16; o; o >>= 1) s += __shfl_xor_sync(0xffffffffu, s, o);
    __shared__ float sm[8];
    if ((threadIdx.x & 31) == 0) sm[threadIdx.x >> 5] = s;
    __syncthreads();
    if (threadIdx.x < 8) {
        float v = sm[threadIdx.x];
        for (int o = 4; o; o >>= 1) v += __shfl_xor_sync(0xffu, v, o);
        if (threadIdx.x == 0) g_x0[bc] = v * (1.0f / 4096.0f);
    }
}

__global__ void gate_kernel(const float* __restrict__ g1, const float* __restrict__ g2,
                            const float* __restrict__ g3, const float* __restrict__ g4,
                            float* __restrict__ loss_out) {
    int lane = threadIdx.x;
    int g = lane >> 3, b = lane & 7;
    const float* G = (g == 0) ? g1 : (g == 1) ? g2 : (g == 2) ? g3 : g4;
    const float* x0 = &g_x0[b * CC];
    float lg[8];
#pragma unroll
    for (int e = 0; e < 8; e++) lg[e] = 0.f;
    for (int c = 0; c < CC; c++) {
        float xv = x0[c];
#pragma unroll
        for (int e = 0; e < 8; e++) lg[e] += xv * G[c * 8 + e];
    }
    float m = lg[0];
#pragma unroll
    for (int e = 1; e < 8; e++) m = fmaxf(m, lg[e]);
    float p[8], sum = 0.f;
#pragma unroll
    for (int e = 0; e < 8; e++) { p[e] = expf(lg[e] - m); sum += p[e]; }
    float inv = 1.f / sum;
#pragma unroll
    for (int e = 0; e < 8; e++) p[e] *= inv;
    int i1 = 0;
#pragma unroll
    for (int e = 1; e < 8; e++) if (p[e] > p[i1]) i1 = e;
    int i2 = (i1 == 0) ? 1 : 0;
#pragma unroll
    for (int e = 0; e < 8; e++) { if (e == i1 || e == i2) continue; if (p[e] > p[i2]) i2 = e; }
    float m2 = fmaxf(p[i1], p[i2]);
    float e1 = expf(p[i1] - m2), e2 = expf(p[i2] - m2);
    float winv = 1.f / (e1 + e2);
    float* wrow = &g_w[(g * 8 + b) * 8];
#pragma unroll
    for (int e = 0; e < 8; e++) wrow[e] = 0.f;
    wrow[i1] = e1 * winv;
    wrow[i2] = e2 * winv;
    float u[8];
#pragma unroll
    for (int e = 0; e < 8; e++) {
        u[e] = p[e];
        for (int o = 1; o < 8; o <<= 1) u[e] += __shfl_xor_sync(0xffffffffu, u[e], o);
    }
    __shared__ float sl[4];
    if (b == 0) {
        float mu = 0.f;
#pragma unroll
        for (int e = 0; e < 8; e++) mu += u[e];
        mu *= (1.0f / 8.0f);
        float var = 0.f;
#pragma unroll
        for (int e = 0; e < 8; e++) { float d = u[e] - mu; var += d * d; }
        var *= (1.0f / 7.0f);
        sl[g] = var / (mu * mu + 1e-10f);
    }
    __syncwarp();
    if (lane == 0) loss_out[0] = sl[0] + sl[1] + sl[2] + sl[3];
}

__device__ __forceinline__ uint32_t packh2(float a, float b) {
    __half2 h; h.x = __float2half_rn(a); h.y = __float2half_rn(b);
    return *(uint32_t*)&h;
}

// merged prep: blocks 0..143 -> W_caps chunk images, 144..159 -> W_proj images
__global__ void prep_all(const float* __restrict__ Wc_all,
                         const float* __restrict__ Wp_all) {
    if (blockIdx.x < EE * 18) {
        int e = blockIdx.x / 18, cc = blockIdx.x % 18;
        int j = cc >> 1, h = cc & 1;
        const float* Wc = Wc_all + (size_t)e * (CC * 1152);
        uint32_t* oh = g_wc_f16 + (size_t)blockIdx.x * 4096;
#pragma unroll 4
        for (int idx = threadIdx.x; idx < 4096; idx += 256) {
            int r = idx >> 6, cop = idx & 63;
            int co = cop * 2, ci = h * 64 + r;
            float v0 = __ldg(Wc + (size_t)co * 1152 + ci * 9 + j);
            float v1 = __ldg(Wc + (size_t)(co + 1) * 1152 + ci * 9 + j);
            uint32_t woff = (r * 256 + ((co * 2) ^ ((r & 7) << 4))) >> 2;
            oh[woff] = packh2(v0, v1);
        }
    } else {
        int k = blockIdx.x - EE * 18;
        int e = k >> 1, h = k & 1;
        const float* Wp = Wp_all + (size_t)e * 16384;
        uint32_t* oh = g_wp_f16 + (size_t)k * 4096;
#pragma unroll 4
        for (int idx = threadIdx.x; idx < 4096; idx += 256) {
            int r = idx >> 6, cop = idx & 63;
            int co = cop * 2, ci = h * 64 + r;
            float v0 = __ldg(Wp + (size_t)co * 128 + ci);
            float v1 = __ldg(Wp + (size_t)(co + 1) * 128 + ci);
            uint32_t woff = (r * 256 + ((co * 2) ^ ((r & 7) << 4))) >> 2;
            oh[woff] = packh2(v0, v1);
        }
    }
}

// ---------------------------------------------------------------------------
// Main kernel (round 15): 512 threads (16 warps, 4/SMSP), warp tile 16px x 64co.
// Same smem layout and pipeline as R13.
// ---------------------------------------------------------------------------

#define SXH   0                    // x fp16: 264 rows x 256B = 67584
#define WOFF  67584                // 4 x 16KB buffers (multi-use)
#define SWG   133120
#define SPARTB 133248              // 2 x 128 floats
#define SSCB  134272               // 128 floats
#define SMEM_BYTES 134784

__device__ __forceinline__ void ldsm4(uint32_t a, uint32_t* r) {
    asm volatile("ldmatrix.sync.aligned.m8n8.x4.shared.b16 {%0,%1,%2,%3}, [%4];"
                 : "=r"(r[0]), "=r"(r[1]), "=r"(r[2]), "=r"(r[3]) : "r"(a));
}
__device__ __forceinline__ void ldsm4t(uint32_t a, uint32_t* r) {
    asm volatile("ldmatrix.sync.aligned.m8n8.x4.trans.shared.b16 {%0,%1,%2,%3}, [%4];"
                 : "=r"(r[0]), "=r"(r[1]), "=r"(r[2]), "=r"(r[3]) : "r"(a));
}
__device__ __forceinline__ void mma_fp(float* d, const uint32_t* a,
                                       uint32_t b0, uint32_t b1) {
    asm volatile(
        "mma.sync.aligned.m16n8k16.row.col.f32.f16.f16.f32 "
        "{%0,%1,%2,%3},{%4,%5,%6,%7},{%8,%9},{%0,%1,%2,%3};"
        : "+f"(d[0]), "+f"(d[1]), "+f"(d[2]), "+f"(d[3])
        : "r"(a[0]), "r"(a[1]), "r"(a[2]), "r"(a[3]), "r"(b0), "r"(b1));
}
__device__ __forceinline__ uint32_t amat_addr(uint32_t base, int R0, int ci0, int lane) {
    int sel = lane >> 3;
    int r = R0 + (lane & 7) + ((sel & 1) << 3);
    int cb = (ci0 + ((sel >> 1) << 3)) * 2;
    return base + r * 256 + (cb ^ ((r & 7) << 4));
}
__device__ __forceinline__ void cp16s(uint32_t dst, const void* src) {
    asm volatile("cp.async.ca.shared.global [%0], [%1], 16;" :: "r"(dst), "l"(src));
}
#define CP_COMMIT() asm volatile("cp.async.commit_group;")
#define CP_WAIT2()  asm volatile("cp.async.wait_group 2;")
#define CP_WAIT1()  asm volatile("cp.async.wait_group 1;")
#define CP_WAIT0()  asm volatile("cp.async.wait_group 0;")

__global__ void __launch_bounds__(512, 1)
moe_main(const float* __restrict__ x,
         const float* __restrict__ bc_all, const float* __restrict__ bp_all,
         float* __restrict__ out) {
    extern __shared__ char smem[];
    const uint32_t sb = (uint32_t)__cvta_generic_to_shared(smem);
    float* swg   = (float*)(smem + SWG);
    float* spart = (float*)(smem + SPARTB);
    float* ssc   = (float*)(smem + SSCB);

    const int tid  = threadIdx.x;
    const int lane = tid & 31;
    const int warp = tid >> 5;         // 0..15
    const int wq = warp >> 1;          // px group of 16 (0..7)
    const int wh = warp & 1;           // co half
    const int blk  = blockIdx.x;
    const int b    = blk >> 5;
    const int row0 = (blk & 31) * 2;
    const int gq = lane >> 2, t4 = lane & 3;
    const int px16 = wq * 16;          // warp's first pixel

    if (tid < 32) {
        int g = tid >> 3, e = tid & 7;
        swg[tid] = g_w[(g * 8 + b) * 8 + e];
    }

    // ---- x strip (4 halo rows, 66 cols, 128 ci), fp16 swizzled ----
    {
        const float* xb = x + (size_t)b * IMG;
        for (int it = 0; it < 32; ++it) {
            int rid = warp + it * 16;          // 0..511 = gry*128+ci
            int gry = rid >> 7, ci = rid & 127;
            int gr = row0 - 1 + gry;
#pragma unroll
            for (int cl = 0; cl < 3; ++cl) {
                int c = lane + cl * 32;
                if (cl == 2 && lane >= 2) break;
                int gc = c - 1;
                float v = 0.f;
                if ((unsigned)gr < 64u && (unsigned)gc < 64u)
                    v = xb[ci * HWPIX + gr * 64 + gc];
                int R = gry * 66 + c;
                uint32_t off = R * 256 + ((ci * 2) ^ ((R & 7) << 4));
                *(__half*)(smem + SXH + off) = __float2half_rn(v);
            }
        }
    }

    float acc[8][4];

    for (int e = 0; e < EE; ++e) {
        float we0 = swg[e], we1 = swg[8 + e], we2 = swg[16 + e], we3 = swg[24 + e];
        __syncthreads();
        if (we0 == 0.f && we1 == 0.f && we2 == 0.f && we3 == 0.f) continue;

        auto loadW = [&](int cc, int bf) {
            const uint32_t* src = g_wc_f16 + (size_t)(e * 18 + cc) * 4096;
#pragma unroll
            for (int k = 0; k < 2; ++k) {
                int i = tid + k * 512;
                cp16s(sb + WOFF + bf * 16384 + i * 16, src + i * 4);
            }
            CP_COMMIT();
        };

        loadW(0, 0);
        loadW(1, 1);
        loadW(2, 2);
#pragma unroll
        for (int f = 0; f < 8; ++f)
#pragma unroll
            for (int i = 0; i < 4; ++i) acc[f][i] = 0.f;

        // ---- GEMM1: 18 chunks, quad-buffered, fragment-pipelined inner ----
        for (int cc = 0; cc < 18; ++cc) {
            if (cc < 16) { CP_WAIT2(); } else if (cc == 16) { CP_WAIT1(); } else { CP_WAIT0(); }
            __syncthreads();
            if (cc + 3 < 18) loadW(cc + 3, (cc + 3) & 3);

            const int j = cc >> 1;
            const int ky = j / 3, kx = j - 3 * (j / 3);
            const int h = cc & 1;
            const uint32_t whb = sb + WOFF + (cc & 3) * 16384;
            const int R0 = (px16 >> 6) * 66 + (px16 & 63) + ky * 66 + kx;

            uint32_t ah[2][4], bh[2][4][4];
            ldsm4(amat_addr(sb + SXH, R0, h * 64, lane), ah[0]);
#pragma unroll
            for (int nn = 0; nn < 4; ++nn)
                ldsm4t(amat_addr(whb, 0, wh * 64 + nn * 16, lane), bh[0][nn]);
#pragma unroll
            for (int ks = 0; ks < 4; ++ks) {
                const int cur = ks & 1, nst = cur ^ 1;
                if (ks < 3) {
                    const int ci0 = h * 64 + (ks + 1) * 16;
                    ldsm4(amat_addr(sb + SXH, R0, ci0, lane), ah[nst]);
#pragma unroll
                    for (int nn = 0; nn < 4; ++nn)
                        ldsm4t(amat_addr(whb, (ks + 1) * 16, wh * 64 + nn * 16, lane), bh[nst][nn]);
                }
#pragma unroll
                for (int nn = 0; nn < 4; ++nn) {
                    mma_fp(acc[nn * 2], ah[cur], bh[cur][nn][0], bh[cur][nn][1]);
                    mma_fp(acc[nn * 2 + 1], ah[cur], bh[cur][nn][2], bh[cur][nn][3]);
                }
            }
        }
        __syncthreads();   // all buffers free

        // prefetch both W_proj half-images into buffers 2,3
        {
            const uint32_t* pH = g_wp_f16 + (size_t)e * 8192;
#pragma unroll
            for (int k = 0; k < 4; ++k) {
                int i = tid + k * 512;
                cp16s(sb + WOFF + 32768 + i * 16, pH + i * 4);
            }
            CP_COMMIT();
        }

        // ---- bias + per-pixel sum of squares ----
        {
            float sa = 0.f, sb2 = 0.f;
#pragma unroll
            for (int f = 0; f < 8; ++f) {
                int co = wh * 64 + f * 8 + t4 * 2;
                float bc0 = __ldg(&bc_all[e * CC + co]);
                float bc1 = __ldg(&bc_all[e * CC + co + 1]);
                acc[f][0] += bc0; acc[f][1] += bc1;
                acc[f][2] += bc0; acc[f][3] += bc1;
                sa = fmaf(acc[f][0], acc[f][0], sa);
                sa = fmaf(acc[f][1], acc[f][1], sa);
                sb2 = fmaf(acc[f][2], acc[f][2], sb2);
                sb2 = fmaf(acc[f][3], acc[f][3], sb2);
            }
            sa += __shfl_xor_sync(0xffffffffu, sa, 1);
            sa += __shfl_xor_sync(0xffffffffu, sa, 2);
            sb2 += __shfl_xor_sync(0xffffffffu, sb2, 1);
            sb2 += __shfl_xor_sync(0xffffffffu, sb2, 2);
            if (t4 == 0) {
                int pxa = px16 + gq;
                spart[wh * 128 + pxa] = sa;
                spart[wh * 128 + pxa + 8] = sb2;
            }
        }
        __syncthreads();
        if (tid < 128) {
            float sn = spart[tid] + spart[128 + tid];
            ssc[tid] = sn / (1.f + sn) / (sqrtf(sn) + 1e-8f);
        }
        __syncthreads();

        // ---- scale + stage u into buffers 0,1 (128 px rows x 256B, swizzled) ----
        {
            int pxa = px16 + gq;
            float s0 = ssc[pxa], s1 = ssc[pxa + 8];
#pragma unroll
            for (int f = 0; f < 8; ++f) {
                int cb = (wh * 64 + f * 8 + t4 * 2) * 2;
                uint32_t w0 = packh2(acc[f][0] * s0, acc[f][1] * s0);
                uint32_t o0 = pxa * 256 + (cb ^ ((pxa & 7) << 4));
                *(uint32_t*)(smem + WOFF + o0) = w0;
                uint32_t w1 = packh2(acc[f][2] * s1, acc[f][3] * s1);
                int px2 = pxa + 8;
                uint32_t o1 = px2 * 256 + (cb ^ ((px2 & 7) << 4));
                *(uint32_t*)(smem + WOFF + o1) = w1;
            }
        }
        CP_WAIT0();
        __syncthreads();

        // ---- GEMM2: K=128, fragment-pipelined (u in bufs 0-1, Wp in bufs 2-3) ----
#pragma unroll
        for (int f = 0; f < 8; ++f)
#pragma unroll
            for (int i = 0; i < 4; ++i) acc[f][i] = 0.f;
        {
            uint32_t ah[2][4], bh[2][4][4];
            auto loadF2 = [&](int ks, int st) {
                ldsm4(amat_addr(sb + WOFF, px16, ks * 16, lane), ah[st]);
                uint32_t wpb = sb + WOFF + 32768 + (ks >> 2) * 16384;
                int kr = (ks & 3) * 16;
#pragma unroll
                for (int nn = 0; nn < 4; ++nn)
                    ldsm4t(amat_addr(wpb, kr, wh * 64 + nn * 16, lane), bh[st][nn]);
            };
            loadF2(0, 0);
#pragma unroll
            for (int ks = 0; ks < 8; ++ks) {
                const int cur = ks & 1, nst = cur ^ 1;
                if (ks < 7) loadF2(ks + 1, nst);
#pragma unroll
                for (int nn = 0; nn < 4; ++nn) {
                    mma_fp(acc[nn * 2], ah[cur], bh[cur][nn][0], bh[cur][nn][1]);
                    mma_fp(acc[nn * 2 + 1], ah[cur], bh[cur][nn][2], bh[cur][nn][3]);
                }
            }
        }
        __syncthreads();   // done reading u/Wp; region reusable for staging

        // ---- v = acc + bp -> scratch (staged, coalesced float4 writes) ----
        float* stg = (float*)(smem + WOFF);   // [64 co][132]
        for (int r = 0; r < 2; ++r) {
            if (wh == r) {
                int pxa = px16 + gq;
#pragma unroll
                for (int f = 0; f < 8; ++f) {
                    int cl = f * 8 + t4 * 2;
                    float bp0 = __ldg(&bp_all[e * CC + r * 64 + cl]);
                    float bp1 = __ldg(&bp_all[e * CC + r * 64 + cl + 1]);
                    stg[cl * 132 + pxa]           = acc[f][0] + bp0;
                    stg[(cl + 1) * 132 + pxa]     = acc[f][1] + bp1;
                    stg[cl * 132 + pxa + 8]       = acc[f][2] + bp0;
                    stg[(cl + 1) * 132 + pxa + 8] = acc[f][3] + bp1;
                }
            }
            __syncthreads();
            float* dst = g_scr + (size_t)(e * NBLK + blk) * 16384 + r * 64 * 128;
#pragma unroll
            for (int k = 0; k < 4; ++k) {
                int i = tid + k * 512;
                int cl = i >> 5, p4 = (i & 31) * 4;
                float4 v = *(float4*)&stg[cl * 132 + p4];
                *(float4*)&dst[cl * 128 + p4] = v;
            }
            __syncthreads();
        }
    }

    // ---- combine: y_g = sum_e w_ge * v_e ----
    __syncthreads();
#pragma unroll 1
    for (int k = 0; k < 8; ++k) {
        int i = tid + k * 512;
        int co = i >> 5, p4 = (i & 31) * 4;
        float4 y0 = {0, 0, 0, 0}, y1 = y0, y2 = y0, y3 = y0;
#pragma unroll
        for (int e = 0; e < EE; ++e) {
            float a0 = swg[e], a1 = swg[8 + e], a2 = swg[16 + e], a3 = swg[24 + e];
            if (a0 == 0.f && a1 == 0.f && a2 == 0.f && a3 == 0.f) continue;
            float4 v = *(const float4*)(g_scr + (size_t)(e * NBLK + blk) * 16384 + co * 128 + p4);
            y0.x += a0 * v.x; y0.y += a0 * v.y; y0.z += a0 * v.z; y0.w += a0 * v.w;
            y1.x += a1 * v.x; y1.y += a1 * v.y; y1.z += a1 * v.z; y1.w += a1 * v.w;
            y2.x += a2 * v.x; y2.y += a2 * v.y; y2.z += a2 * v.z; y2.w += a2 * v.w;
            y3.x += a3 * v.x; y3.y += a3 * v.y; y3.z += a3 * v.z; y3.w += a3 * v.w;
        }
        int r2 = p4 >> 6, col = p4 & 63;
        size_t gidx = (size_t)b * IMG + (size_t)co * HWPIX + (size_t)(row0 + r2) * 64 + col;
        *(float4*)(out + gidx) = y0;
        *(float4*)(out + YSZ + gidx) = y1;
        *(float4*)(out + 2 * YSZ + gidx) = y2;
        *(float4*)(out + 3 * YSZ + gidx) = y3;
    }
}

// ---------------------------------------------------------------------------
extern "C" void kernel_launch(void* const* d_in, const int* in_sizes, int n_in,
                              void* d_out, int out_size) {
    const float* x  = (const float*)d_in[0];
    const float* g1 = (const float*)d_in[1];
    const float* g2 = (const float*)d_in[2];
    const float* g3 = (const float*)d_in[3];
    const float* g4 = (const float*)d_in[4];
    const float* Wc = (const float*)d_in[5];
    const float* bc = (const float*)d_in[6];
    const float* Wp = (const float*)d_in[7];
    const float* bp = (const float*)d_in[8];
    float* out = (float*)d_out;

    cudaFuncSetAttribute(moe_main, cudaFuncAttributeMaxDynamicSharedMemorySize, SMEM_BYTES);

    mean_kernel<<<BB * CC, 256>>>(x);
    gate_kernel<<<1, 32>>>(g1, g2, g3, g4, out + (out_size - 1));
    prep_all<<<EE * 18 + EE * 2, 256>>>(Wc, Wp);
    moe_main<<<NBLK, 512, SMEM_BYTES>>>(x, bc, bp, out);   // launch #4 -> ncu target
}

// round 16
// speedup vs baseline: 1.1637x; 1.0984x over previous
#include <cuda_runtime.h>
#include <cuda_fp16.h>
#include <cstdint>

#define CC   128
#define BB   8
#define EE   8
#define NG   4
#define HWPIX 4096
#define IMG  524288   // 128*64*64
#define YSZ  4194304  // 8*128*64*64
#define NBLK 512      // 8 b x 64 rows

__device__ float g_x0[BB * CC];
__device__ float g_w[NG * BB * EE];

// Pre-converted fp16 weights (swizzled 16KB chunk images)
__device__ uint32_t g_wc_f16[EE * 18 * 4096];
__device__ uint32_t g_wp_f16[EE * 2 * 4096];
// per-expert v staging: [e][blk][co][px64]
__device__ float g_scr[(size_t)EE * NBLK * 8192];

// ---------------------------------------------------------------------------
__global__ void mean_kernel(const float* __restrict__ x) {
    int bc = blockIdx.x;
    const float4* p = (const float4*)(x + (size_t)bc * HWPIX);
    float s = 0.f;
    for (int i = threadIdx.x; i < 1024; i += 256) { float4 v = p[i]; s += (v.x + v.y) + (v.z + v.w); }
    for (int o = 16; o; o >>= 1) s += __shfl_xor_sync(0xffffffffu, s, o);
    __shared__ float sm[8];
    if ((threadIdx.x & 31) == 0) sm[threadIdx.x >> 5] = s;
    __syncthreads();
    if (threadIdx.x < 8) {
        float v = sm[threadIdx.x];
        for (int o = 4; o; o >>= 1) v += __shfl_xor_sync(0xffu, v, o);
        if (threadIdx.x == 0) g_x0[bc] = v * (1.0f / 4096.0f);
    }
}

__global__ void gate_kernel(const float* __restrict__ g1, const float* __restrict__ g2,
                            const float* __restrict__ g3, const float* __restrict__ g4,
                            float* __restrict__ loss_out) {
    int lane = threadIdx.x;
    int g = lane >> 3, b = lane & 7;
    const float* G = (g == 0) ? g1 : (g == 1) ? g2 : (g == 2) ? g3 : g4;
    const float* x0 = &g_x0[b * CC];
    float lg[8];
#pragma unroll
    for (int e = 0; e < 8; e++) lg[e] = 0.f;
    for (int c = 0; c < CC; c++) {
        float xv = x0[c];
#pragma unroll
        for (int e = 0; e < 8; e++) lg[e] += xv * G[c * 8 + e];
    }
    float m = lg[0];
#pragma unroll
    for (int e = 1; e < 8; e++) m = fmaxf(m, lg[e]);
    float p[8], sum = 0.f;
#pragma unroll
    for (int e = 0; e < 8; e++) { p[e] = expf(lg[e] - m); sum += p[e]; }
    float inv = 1.f / sum;
#pragma unroll
    for (int e = 0; e < 8; e++) p[e] *= inv;
    int i1 = 0;
#pragma unroll
    for (int e = 1; e < 8; e++) if (p[e] > p[i1]) i1 = e;
    int i2 = (i1 == 0) ? 1 : 0;
#pragma unroll
    for (int e = 0; e < 8; e++) { if (e == i1 || e == i2) continue; if (p[e] > p[i2]) i2 = e; }
    float m2 = fmaxf(p[i1], p[i2]);
    float e1 = expf(p[i1] - m2), e2 = expf(p[i2] - m2);
    float winv = 1.f / (e1 + e2);
    float* wrow = &g_w[(g * 8 + b) * 8];
#pragma unroll
    for (int e = 0; e < 8; e++) wrow[e] = 0.f;
    wrow[i1] = e1 * winv;
    wrow[i2] = e2 * winv;
    float u[8];
#pragma unroll
    for (int e = 0; e < 8; e++) {
        u[e] = p[e];
        for (int o = 1; o < 8; o <<= 1) u[e] += __shfl_xor_sync(0xffffffffu, u[e], o);
    }
    __shared__ float sl[4];
    if (b == 0) {
        float mu = 0.f;
#pragma unroll
        for (int e = 0; e < 8; e++) mu += u[e];
        mu *= (1.0f / 8.0f);
        float var = 0.f;
#pragma unroll
        for (int e = 0; e < 8; e++) { float d = u[e] - mu; var += d * d; }
        var *= (1.0f / 7.0f);
        sl[g] = var / (mu * mu + 1e-10f);
    }
    __syncwarp();
    if (lane == 0) loss_out[0] = sl[0] + sl[1] + sl[2] + sl[3];
}

__device__ __forceinline__ uint32_t packh2(float a, float b) {
    __half2 h; h.x = __float2half_rn(a); h.y = __float2half_rn(b);
    return *(uint32_t*)&h;
}

// merged prep: blocks 0..143 -> W_caps chunk images, 144..159 -> W_proj images
__global__ void prep_all(const float* __restrict__ Wc_all,
                         const float* __restrict__ Wp_all) {
    if (blockIdx.x < EE * 18) {
        int e = blockIdx.x / 18, cc = blockIdx.x % 18;
        int j = cc >> 1, h = cc & 1;
        const float* Wc = Wc_all + (size_t)e * (CC * 1152);
        uint32_t* oh = g_wc_f16 + (size_t)blockIdx.x * 4096;
#pragma unroll 4
        for (int idx = threadIdx.x; idx < 4096; idx += 256) {
            int r = idx >> 6, cop = idx & 63;
            int co = cop * 2, ci = h * 64 + r;
            float v0 = __ldg(Wc + (size_t)co * 1152 + ci * 9 + j);
            float v1 = __ldg(Wc + (size_t)(co + 1) * 1152 + ci * 9 + j);
            uint32_t woff = (r * 256 + ((co * 2) ^ ((r & 7) << 4))) >> 2;
            oh[woff] = packh2(v0, v1);
        }
    } else {
        int k = blockIdx.x - EE * 18;
        int e = k >> 1, h = k & 1;
        const float* Wp = Wp_all + (size_t)e * 16384;
        uint32_t* oh = g_wp_f16 + (size_t)k * 4096;
#pragma unroll 4
        for (int idx = threadIdx.x; idx < 4096; idx += 256) {
            int r = idx >> 6, cop = idx & 63;
            int co = cop * 2, ci = h * 64 + r;
            float v0 = __ldg(Wp + (size_t)co * 128 + ci);
            float v1 = __ldg(Wp + (size_t)(co + 1) * 128 + ci);
            uint32_t woff = (r * 256 + ((co * 2) ^ ((r & 7) << 4))) >> 2;
            oh[woff] = packh2(v0, v1);
        }
    }
}

// ---------------------------------------------------------------------------
// Main kernel (round 16): 64px block (1 row), 256 threads, 2 CTAs/SM.
// Warp tile 16px x 64co. 2-buffer weight pipeline (1 sync/chunk).
// ---------------------------------------------------------------------------

#define SXH   0                    // x fp16: 198 rows x 256B = 50688
#define WOFF  50688                // 2 x 16KB buffers
#define SWG   83456                // 32 floats
#define SPARTB 83584               // 2 x 64 floats
#define SSCB  84096                // 64 floats
#define SMEM_BYTES 84352

__device__ __forceinline__ void ldsm4(uint32_t a, uint32_t* r) {
    asm volatile("ldmatrix.sync.aligned.m8n8.x4.shared.b16 {%0,%1,%2,%3}, [%4];"
                 : "=r"(r[0]), "=r"(r[1]), "=r"(r[2]), "=r"(r[3]) : "r"(a));
}
__device__ __forceinline__ void ldsm4t(uint32_t a, uint32_t* r) {
    asm volatile("ldmatrix.sync.aligned.m8n8.x4.trans.shared.b16 {%0,%1,%2,%3}, [%4];"
                 : "=r"(r[0]), "=r"(r[1]), "=r"(r[2]), "=r"(r[3]) : "r"(a));
}
__device__ __forceinline__ void mma_fp(float* d, const uint32_t* a,
                                       uint32_t b0, uint32_t b1) {
    asm volatile(
        "mma.sync.aligned.m16n8k16.row.col.f32.f16.f16.f32 "
        "{%0,%1,%2,%3},{%4,%5,%6,%7},{%8,%9},{%0,%1,%2,%3};"
        : "+f"(d[0]), "+f"(d[1]), "+f"(d[2]), "+f"(d[3])
        : "r"(a[0]), "r"(a[1]), "r"(a[2]), "r"(a[3]), "r"(b0), "r"(b1));
}
__device__ __forceinline__ uint32_t amat_addr(uint32_t base, int R0, int ci0, int lane) {
    int sel = lane >> 3;
    int r = R0 + (lane & 7) + ((sel & 1) << 3);
    int cb = (ci0 + ((sel >> 1) << 3)) * 2;
    return base + r * 256 + (cb ^ ((r & 7) << 4));
}
__device__ __forceinline__ void cp16s(uint32_t dst, const void* src) {
    asm volatile("cp.async.ca.shared.global [%0], [%1], 16;" :: "r"(dst), "l"(src));
}
#define CP_COMMIT() asm volatile("cp.async.commit_group;")
#define CP_WAIT0()  asm volatile("cp.async.wait_group 0;")

__global__ void __launch_bounds__(256, 2)
moe_main(const float* __restrict__ x,
         const float* __restrict__ bc_all, const float* __restrict__ bp_all,
         float* __restrict__ out) {
    extern __shared__ char smem[];
    const uint32_t sb = (uint32_t)__cvta_generic_to_shared(smem);
    float* swg   = (float*)(smem + SWG);
    float* spart = (float*)(smem + SPARTB);
    float* ssc   = (float*)(smem + SSCB);

    const int tid  = threadIdx.x;
    const int lane = tid & 31;
    const int warp = tid >> 5;         // 0..7
    const int wq = warp >> 1;          // px group of 16 (0..3)
    const int wh = warp & 1;           // co half
    const int blk  = blockIdx.x;
    const int b    = blk >> 6;
    const int row  = blk & 63;
    const int gq = lane >> 2, t4 = lane & 3;
    const int px16 = wq * 16;

    if (tid < 32) {
        int g = tid >> 3, e = tid & 7;
        swg[tid] = g_w[(g * 8 + b) * 8 + e];
    }

    // ---- x strip (3 halo rows, 66 cols, 128 ci), fp16 swizzled ----
    {
        const float* xb = x + (size_t)b * IMG;
        for (int it = 0; it < 48; ++it) {
            int rid = warp + it * 8;           // 0..383 = gry*128 + ci
            int gry = rid >> 7, ci = rid & 127;
            int gr = row - 1 + gry;
#pragma unroll
            for (int cl = 0; cl < 3; ++cl) {
                int c = lane + cl * 32;
                if (cl == 2 && lane >= 2) break;
                int gc = c - 1;
                float v = 0.f;
                if ((unsigned)gr < 64u && (unsigned)gc < 64u)
                    v = xb[ci * HWPIX + gr * 64 + gc];
                int R = gry * 66 + c;
                uint32_t off = R * 256 + ((ci * 2) ^ ((R & 7) << 4));
                *(__half*)(smem + SXH + off) = __float2half_rn(v);
            }
        }
    }

    float acc[8][4];

    for (int e = 0; e < EE; ++e) {
        float we0 = swg[e], we1 = swg[8 + e], we2 = swg[16 + e], we3 = swg[24 + e];
        __syncthreads();
        if (we0 == 0.f && we1 == 0.f && we2 == 0.f && we3 == 0.f) continue;

        auto loadW = [&](int cc, int bf) {
            const uint32_t* src = g_wc_f16 + (size_t)(e * 18 + cc) * 4096;
#pragma unroll
            for (int k = 0; k < 4; ++k) {
                int i = tid + k * 256;
                cp16s(sb + WOFF + bf * 16384 + i * 16, src + i * 4);
            }
            CP_COMMIT();
        };

        loadW(0, 0);
#pragma unroll
        for (int f = 0; f < 8; ++f)
#pragma unroll
            for (int i = 0; i < 4; ++i) acc[f][i] = 0.f;

        // ---- GEMM1: 18 chunks, 2 buffers, 1 sync/chunk ----
        for (int cc = 0; cc < 18; ++cc) {
            CP_WAIT0();
            __syncthreads();
            if (cc < 17) loadW(cc + 1, (cc + 1) & 1);

            const int j = cc >> 1;
            const int ky = j / 3, kx = j - 3 * (j / 3);
            const int h = cc & 1;
            const uint32_t whb = sb + WOFF + (cc & 1) * 16384;
            const int R0 = ky * 66 + px16 + kx;
#pragma unroll
            for (int ks = 0; ks < 4; ++ks) {
                const int ci0 = h * 64 + ks * 16;
                uint32_t ah[4];
                ldsm4(amat_addr(sb + SXH, R0, ci0, lane), ah);
#pragma unroll
                for (int nn = 0; nn < 4; ++nn) {
                    uint32_t bh[4];
                    ldsm4t(amat_addr(whb, ks * 16, wh * 64 + nn * 16, lane), bh);
                    mma_fp(acc[nn * 2], ah, bh[0], bh[1]);
                    mma_fp(acc[nn * 2 + 1], ah, bh[2], bh[3]);
                }
            }
        }
        __syncthreads();   // both buffers free

        // cp W_proj half 0 into buf1 (overlaps squash)
        {
            const uint32_t* pH = g_wp_f16 + (size_t)(e * 2 + 0) * 4096;
#pragma unroll
            for (int k = 0; k < 4; ++k) {
                int i = tid + k * 256;
                cp16s(sb + WOFF + 16384 + i * 16, pH + i * 4);
            }
            CP_COMMIT();
        }

        // ---- bias + per-pixel sum of squares ----
        {
            float sa = 0.f, sb2 = 0.f;
#pragma unroll
            for (int f = 0; f < 8; ++f) {
                int co = wh * 64 + f * 8 + t4 * 2;
                float bc0 = __ldg(&bc_all[e * CC + co]);
                float bc1 = __ldg(&bc_all[e * CC + co + 1]);
                acc[f][0] += bc0; acc[f][1] += bc1;
                acc[f][2] += bc0; acc[f][3] += bc1;
                sa = fmaf(acc[f][0], acc[f][0], sa);
                sa = fmaf(acc[f][1], acc[f][1], sa);
                sb2 = fmaf(acc[f][2], acc[f][2], sb2);
                sb2 = fmaf(acc[f][3], acc[f][3], sb2);
            }
            sa += __shfl_xor_sync(0xffffffffu, sa, 1);
            sa += __shfl_xor_sync(0xffffffffu, sa, 2);
            sb2 += __shfl_xor_sync(0xffffffffu, sb2, 1);
            sb2 += __shfl_xor_sync(0xffffffffu, sb2, 2);
            if (t4 == 0) {
                int pxa = px16 + gq;
                spart[wh * 64 + pxa] = sa;
                spart[wh * 64 + pxa + 8] = sb2;
            }
        }
        __syncthreads();
        if (tid < 64) {
            float sn = spart[tid] + spart[64 + tid];
            ssc[tid] = sn / (1.f + sn) / (sqrtf(sn) + 1e-8f);
        }
        __syncthreads();

        // ---- scale + stage u into buf0 (64 px rows x 256B, swizzled) ----
        {
            int pxa = px16 + gq;
            float s0 = ssc[pxa], s1 = ssc[pxa + 8];
#pragma unroll
            for (int f = 0; f < 8; ++f) {
                int cb = (wh * 64 + f * 8 + t4 * 2) * 2;
                uint32_t w0 = packh2(acc[f][0] * s0, acc[f][1] * s0);
                uint32_t o0 = pxa * 256 + (cb ^ ((pxa & 7) << 4));
                *(uint32_t*)(smem + WOFF + o0) = w0;
                uint32_t w1 = packh2(acc[f][2] * s1, acc[f][3] * s1);
                int px2 = pxa + 8;
                uint32_t o1 = px2 * 256 + (cb ^ ((px2 & 7) << 4));
                *(uint32_t*)(smem + WOFF + o1) = w1;
            }
        }
        CP_WAIT0();
        __syncthreads();

        // ---- GEMM2: K=128 in 2 ci-half passes (u buf0, Wp half buf1) ----
#pragma unroll
        for (int f = 0; f < 8; ++f)
#pragma unroll
            for (int i = 0; i < 4; ++i) acc[f][i] = 0.f;

        for (int h2 = 0; h2 < 2; ++h2) {
#pragma unroll
            for (int ks = 0; ks < 4; ++ks) {
                uint32_t ah[4];
                ldsm4(amat_addr(sb + WOFF, px16, h2 * 64 + ks * 16, lane), ah);
#pragma unroll
                for (int nn = 0; nn < 4; ++nn) {
                    uint32_t bh[4];
                    ldsm4t(amat_addr(sb + WOFF + 16384, ks * 16, wh * 64 + nn * 16, lane), bh);
                    mma_fp(acc[nn * 2], ah, bh[0], bh[1]);
                    mma_fp(acc[nn * 2 + 1], ah, bh[2], bh[3]);
                }
            }
            if (h2 == 0) {
                __syncthreads();    // all warps done reading buf1 (half 0)
                const uint32_t* pH = g_wp_f16 + (size_t)(e * 2 + 1) * 4096;
#pragma unroll
                for (int k = 0; k < 4; ++k) {
                    int i = tid + k * 256;
                    cp16s(sb + WOFF + 16384 + i * 16, pH + i * 4);
                }
                CP_COMMIT();
                CP_WAIT0();
                __syncthreads();
            }
        }
        __syncthreads();   // done reading bufs; region reusable for staging

        // ---- v = acc + bp -> staging [128co][64px] -> scratch ----
        float* stg = (float*)(smem + WOFF);
        {
            int pxa = px16 + gq;
#pragma unroll
            for (int f = 0; f < 8; ++f) {
                int cl = wh * 64 + f * 8 + t4 * 2;
                float bp0 = __ldg(&bp_all[e * CC + cl]);
                float bp1 = __ldg(&bp_all[e * CC + cl + 1]);
                stg[cl * 64 + pxa]           = acc[f][0] + bp0;
                stg[(cl + 1) * 64 + pxa]     = acc[f][1] + bp1;
                stg[cl * 64 + pxa + 8]       = acc[f][2] + bp0;
                stg[(cl + 1) * 64 + pxa + 8] = acc[f][3] + bp1;
            }
        }
        __syncthreads();
        {
            float* dst = g_scr + (size_t)(e * NBLK + blk) * 8192;
#pragma unroll
            for (int k = 0; k < 8; ++k) {
                int i = tid + k * 256;
                int cl = i >> 4, p4 = (i & 15) * 4;
                float4 v = *(float4*)&stg[cl * 64 + p4];
                *(float4*)&dst[cl * 64 + p4] = v;
            }
        }
        __syncthreads();
    }

    // ---- combine: y_g = sum_e w_ge * v_e ----
    __syncthreads();
#pragma unroll 1
    for (int k = 0; k < 8; ++k) {
        int i = tid + k * 256;                 // 0..2047 float4 ids
        int co = i >> 4, p4 = (i & 15) * 4;
        float4 y0 = {0, 0, 0, 0}, y1 = y0, y2 = y0, y3 = y0;
#pragma unroll
        for (int e = 0; e < EE; ++e) {
            float a0 = swg[e], a1 = swg[8 + e], a2 = swg[16 + e], a3 = swg[24 + e];
            if (a0 == 0.f && a1 == 0.f && a2 == 0.f && a3 == 0.f) continue;
            float4 v = *(const float4*)(g_scr + (size_t)(e * NBLK + blk) * 8192 + co * 64 + p4);
            y0.x += a0 * v.x; y0.y += a0 * v.y; y0.z += a0 * v.z; y0.w += a0 * v.w;
            y1.x += a1 * v.x; y1.y += a1 * v.y; y1.z += a1 * v.z; y1.w += a1 * v.w;
            y2.x += a2 * v.x; y2.y += a2 * v.y; y2.z += a2 * v.z; y2.w += a2 * v.w;
            y3.x += a3 * v.x; y3.y += a3 * v.y; y3.z += a3 * v.z; y3.w += a3 * v.w;
        }
        size_t gidx = (size_t)b * IMG + (size_t)co * HWPIX + (size_t)row * 64 + p4;
        *(float4*)(out + gidx) = y0;
        *(float4*)(out + YSZ + gidx) = y1;
        *(float4*)(out + 2 * YSZ + gidx) = y2;
        *(float4*)(out + 3 * YSZ + gidx) = y3;
    }
}

// ---------------------------------------------------------------------------
extern "C" void kernel_launch(void* const* d_in, const int* in_sizes, int n_in,
                              void* d_out, int out_size) {
    const float* x  = (const float*)d_in[0];
    const float* g1 = (const float*)d_in[1];
    const float* g2 = (const float*)d_in[2];
    const float* g3 = (const float*)d_in[3];
    const float* g4 = (const float*)d_in[4];
    const float* Wc = (const float*)d_in[5];
    const float* bc = (const float*)d_in[6];
    const float* Wp = (const float*)d_in[7];
    const float* bp = (const float*)d_in[8];
    float* out = (float*)d_out;

    cudaFuncSetAttribute(moe_main, cudaFuncAttributeMaxDynamicSharedMemorySize, SMEM_BYTES);

    mean_kernel<<<BB * CC, 256>>>(x);
    gate_kernel<<<1, 32>>>(g1, g2, g3, g4, out + (out_size - 1));
    prep_all<<<EE * 18 + EE * 2, 256>>>(Wc, Wp);
    moe_main<<<NBLK, 256, SMEM_BYTES>>>(x, bc, bp, out);   // launch #4 -> ncu target
}

// round 17
// speedup vs baseline: 1.1699x; 1.0053x over previous
#include <cuda_runtime.h>
#include <cuda_fp16.h>
#include <cstdint>

#define CC   128
#define BB   8
#define EE   8
#define NG   4
#define HWPIX 4096
#define IMG  524288   // 128*64*64
#define YSZ  4194304  // 8*128*64*64
#define NBLK 512      // 8 b x 64 rows

__device__ float g_x0[BB * CC];
__device__ float g_w[NG * BB * EE];

// Pre-converted fp16 weights: [co rows 128][ci cols 64] 128B rows, swizzled
__device__ uint32_t g_wc_f16[EE * 18 * 4096];
__device__ uint32_t g_wp_f16[EE * 2 * 4096];
// per-expert v staging: [e][blk][co][px64]
__device__ float g_scr[(size_t)EE * NBLK * 8192];

// ---------------------------------------------------------------------------
__global__ void mean_kernel(const float* __restrict__ x) {
    int bc = blockIdx.x;
    const float4* p = (const float4*)(x + (size_t)bc * HWPIX);
    float s = 0.f;
    for (int i = threadIdx.x; i < 1024; i += 256) { float4 v = p[i]; s += (v.x + v.y) + (v.z + v.w); }
    for (int o = 16; o; o >>= 1) s += __shfl_xor_sync(0xffffffffu, s, o);
    __shared__ float sm[8];
    if ((threadIdx.x & 31) == 0) sm[threadIdx.x >> 5] = s;
    __syncthreads();
    if (threadIdx.x < 8) {
        float v = sm[threadIdx.x];
        for (int o = 4; o; o >>= 1) v += __shfl_xor_sync(0xffu, v, o);
        if (threadIdx.x == 0) g_x0[bc] = v * (1.0f / 4096.0f);
    }
}

__global__ void gate_kernel(const float* __restrict__ g1, const float* __restrict__ g2,
                            const float* __restrict__ g3, const float* __restrict__ g4,
                            float* __restrict__ loss_out) {
    int lane = threadIdx.x;
    int g = lane >> 3, b = lane & 7;
    const float* G = (g == 0) ? g1 : (g == 1) ? g2 : (g == 2) ? g3 : g4;
    const float* x0 = &g_x0[b * CC];
    float lg[8];
#pragma unroll
    for (int e = 0; e < 8; e++) lg[e] = 0.f;
    for (int c = 0; c < CC; c++) {
        float xv = x0[c];
#pragma unroll
        for (int e = 0; e < 8; e++) lg[e] += xv * G[c * 8 + e];
    }
    float m = lg[0];
#pragma unroll
    for (int e = 1; e < 8; e++) m = fmaxf(m, lg[e]);
    float p[8], sum = 0.f;
#pragma unroll
    for (int e = 0; e < 8; e++) { p[e] = expf(lg[e] - m); sum += p[e]; }
    float inv = 1.f / sum;
#pragma unroll
    for (int e = 0; e < 8; e++) p[e] *= inv;
    int i1 = 0;
#pragma unroll
    for (int e = 1; e < 8; e++) if (p[e] > p[i1]) i1 = e;
    int i2 = (i1 == 0) ? 1 : 0;
#pragma unroll
    for (int e = 0; e < 8; e++) { if (e == i1 || e == i2) continue; if (p[e] > p[i2]) i2 = e; }
    float m2 = fmaxf(p[i1], p[i2]);
    float e1 = expf(p[i1] - m2), e2 = expf(p[i2] - m2);
    float winv = 1.f / (e1 + e2);
    float* wrow = &g_w[(g * 8 + b) * 8];
#pragma unroll
    for (int e = 0; e < 8; e++) wrow[e] = 0.f;
    wrow[i1] = e1 * winv;
    wrow[i2] = e2 * winv;
    float u[8];
#pragma unroll
    for (int e = 0; e < 8; e++) {
        u[e] = p[e];
        for (int o = 1; o < 8; o <<= 1) u[e] += __shfl_xor_sync(0xffffffffu, u[e], o);
    }
    __shared__ float sl[4];
    if (b == 0) {
        float mu = 0.f;
#pragma unroll
        for (int e = 0; e < 8; e++) mu += u[e];
        mu *= (1.0f / 8.0f);
        float var = 0.f;
#pragma unroll
        for (int e = 0; e < 8; e++) { float d = u[e] - mu; var += d * d; }
        var *= (1.0f / 7.0f);
        sl[g] = var / (mu * mu + 1e-10f);
    }
    __syncwarp();
    if (lane == 0) loss_out[0] = sl[0] + sl[1] + sl[2] + sl[3];
}

__device__ __forceinline__ uint32_t packh2(float a, float b) {
    __half2 h; h.x = __float2half_rn(a); h.y = __float2half_rn(b);
    return *(uint32_t*)&h;
}

// merged prep: blocks 0..143 -> W_caps images, 144..159 -> W_proj images
// Image layout: [co row 0..127][ci_local col 0..63] fp16, 128B rows,
// byte off = co*128 + ((ci_local*2) ^ ((co&7)<<4)); pack pairs along ci.
__global__ void prep_all(const float* __restrict__ Wc_all,
                         const float* __restrict__ Wp_all) {
    if (blockIdx.x < EE * 18) {
        int e = blockIdx.x / 18, cc = blockIdx.x % 18;
        int j = cc >> 1, h = cc & 1;
        const float* Wc = Wc_all + (size_t)e * (CC * 1152);
        uint32_t* oh = g_wc_f16 + (size_t)blockIdx.x * 4096;
#pragma unroll 4
        for (int idx = threadIdx.x; idx < 4096; idx += 256) {
            int co = idx >> 5, p = idx & 31;
            int ci = h * 64 + p * 2;
            float v0 = __ldg(Wc + (size_t)co * 1152 + ci * 9 + j);
            float v1 = __ldg(Wc + (size_t)co * 1152 + (ci + 1) * 9 + j);
            uint32_t woff = (co * 128 + ((p * 4) ^ ((co & 7) << 4))) >> 2;
            oh[woff] = packh2(v0, v1);
        }
    } else {
        int k = blockIdx.x - EE * 18;
        int e = k >> 1, h = k & 1;
        const float* Wp = Wp_all + (size_t)e * 16384;
        uint32_t* oh = g_wp_f16 + (size_t)k * 4096;
#pragma unroll 4
        for (int idx = threadIdx.x; idx < 4096; idx += 256) {
            int co = idx >> 5, p = idx & 31;
            int ci = h * 64 + p * 2;
            float v0 = __ldg(Wp + (size_t)co * 128 + ci);
            float v1 = __ldg(Wp + (size_t)co * 128 + ci + 1);
            uint32_t woff = (co * 128 + ((p * 4) ^ ((co & 7) << 4))) >> 2;
            oh[woff] = packh2(v0, v1);
        }
    }
}

// ---------------------------------------------------------------------------
// Main kernel (round 17): 64px block, 256 thr, 2 CTAs/SM.
// Warp tile 32px x 32co (ph = warp>>2, cq = warp&3). B via NON-trans ldsm
// from [co][ci] images.
// ---------------------------------------------------------------------------

#define SXH   0                    // x fp16: 198 rows x 256B = 50688
#define WOFF  50688                // 2 x 16KB buffers
#define SWG   83456                // 128B
#define SPARTB 83584               // 4 x 64 floats = 1024B
#define SSCB  84608                // 64 floats
#define SMEM_BYTES 84864

__device__ __forceinline__ void ldsm4(uint32_t a, uint32_t* r) {
    asm volatile("ldmatrix.sync.aligned.m8n8.x4.shared.b16 {%0,%1,%2,%3}, [%4];"
                 : "=r"(r[0]), "=r"(r[1]), "=r"(r[2]), "=r"(r[3]) : "r"(a));
}
__device__ __forceinline__ void mma_fp(float* d, const uint32_t* a,
                                       uint32_t b0, uint32_t b1) {
    asm volatile(
        "mma.sync.aligned.m16n8k16.row.col.f32.f16.f16.f32 "
        "{%0,%1,%2,%3},{%4,%5,%6,%7},{%8,%9},{%0,%1,%2,%3};"
        : "+f"(d[0]), "+f"(d[1]), "+f"(d[2]), "+f"(d[3])
        : "r"(a[0]), "r"(a[1]), "r"(a[2]), "r"(a[3]), "r"(b0), "r"(b1));
}
// A tables: 256B rows (x strip / u table)
__device__ __forceinline__ uint32_t amat_addr(uint32_t base, int R0, int ci0, int lane) {
    int sel = lane >> 3;
    int r = R0 + (lane & 7) + ((sel & 1) << 3);
    int cb = (ci0 + ((sel >> 1) << 3)) * 2;
    return base + r * 256 + (cb ^ ((r & 7) << 4));
}
// B images: 128B rows [co][ci]; non-trans ldsm: rows = co (n), cols = ci (k)
__device__ __forceinline__ uint32_t bmat_addr(uint32_t base, int co0, int k0, int lane) {
    int sel = lane >> 3;
    int r = co0 + (lane & 7) + ((sel & 1) << 3);
    int cb = (k0 + ((sel >> 1) << 3)) * 2;
    return base + r * 128 + (cb ^ ((r & 7) << 4));
}
__device__ __forceinline__ void cp16s(uint32_t dst, const void* src) {
    asm volatile("cp.async.ca.shared.global [%0], [%1], 16;" :: "r"(dst), "l"(src));
}
#define CP_COMMIT() asm volatile("cp.async.commit_group;")
#define CP_WAIT0()  asm volatile("cp.async.wait_group 0;")

__global__ void __launch_bounds__(256, 2)
moe_main(const float* __restrict__ x,
         const float* __restrict__ bc_all, const float* __restrict__ bp_all,
         float* __restrict__ out) {
    extern __shared__ char smem[];
    const uint32_t sb = (uint32_t)__cvta_generic_to_shared(smem);
    float* swg   = (float*)(smem + SWG);
    float* spart = (float*)(smem + SPARTB);
    float* ssc   = (float*)(smem + SSCB);

    const int tid  = threadIdx.x;
    const int lane = tid & 31;
    const int warp = tid >> 5;         // 0..7
    const int ph = warp >> 2;          // px half (32px)
    const int cq = warp & 3;           // co quarter (32co)
    const int blk  = blockIdx.x;
    const int b    = blk >> 6;
    const int row  = blk & 63;
    const int gq = lane >> 2, t4 = lane & 3;

    if (tid < 32) {
        int g = tid >> 3, e = tid & 7;
        swg[tid] = g_w[(g * 8 + b) * 8 + e];
    }

    // ---- x strip (3 halo rows, 66 cols, 128 ci), fp16 swizzled ----
    {
        const float* xb = x + (size_t)b * IMG;
        for (int it = 0; it < 48; ++it) {
            int rid = warp + it * 8;           // 0..383 = gry*128 + ci
            int gry = rid >> 7, ci = rid & 127;
            int gr = row - 1 + gry;
#pragma unroll
            for (int cl = 0; cl < 3; ++cl) {
                int c = lane + cl * 32;
                if (cl == 2 && lane >= 2) break;
                int gc = c - 1;
                float v = 0.f;
                if ((unsigned)gr < 64u && (unsigned)gc < 64u)
                    v = xb[ci * HWPIX + gr * 64 + gc];
                int R = gry * 66 + c;
                uint32_t off = R * 256 + ((ci * 2) ^ ((R & 7) << 4));
                *(__half*)(smem + SXH + off) = __float2half_rn(v);
            }
        }
    }

    float acc[2][4][4];   // [px frag][n8 within 32co][4]

    for (int e = 0; e < EE; ++e) {
        float we0 = swg[e], we1 = swg[8 + e], we2 = swg[16 + e], we3 = swg[24 + e];
        __syncthreads();
        if (we0 == 0.f && we1 == 0.f && we2 == 0.f && we3 == 0.f) continue;

        auto loadW = [&](int cc, int bf) {
            const uint32_t* src = g_wc_f16 + (size_t)(e * 18 + cc) * 4096;
#pragma unroll
            for (int k = 0; k < 4; ++k) {
                int i = tid + k * 256;
                cp16s(sb + WOFF + bf * 16384 + i * 16, src + i * 4);
            }
            CP_COMMIT();
        };

        loadW(0, 0);
#pragma unroll
        for (int a = 0; a < 2; ++a)
#pragma unroll
            for (int nn = 0; nn < 4; ++nn)
#pragma unroll
                for (int i = 0; i < 4; ++i) acc[a][nn][i] = 0.f;

        // ---- GEMM1: 18 chunks, 2 buffers, 1 sync/chunk ----
        for (int cc = 0; cc < 18; ++cc) {
            CP_WAIT0();
            __syncthreads();
            if (cc < 17) loadW(cc + 1, (cc + 1) & 1);

            const int j = cc >> 1;
            const int ky = j / 3, kx = j - 3 * (j / 3);
            const int h = cc & 1;
            const uint32_t whb = sb + WOFF + (cc & 1) * 16384;
#pragma unroll
            for (int ks = 0; ks < 4; ++ks) {
                const int ci0 = h * 64 + ks * 16;
                uint32_t ah[2][4], bh[2][4];
#pragma unroll
                for (int a = 0; a < 2; ++a) {
                    int R0 = ky * 66 + ph * 32 + a * 16 + kx;
                    ldsm4(amat_addr(sb + SXH, R0, ci0, lane), ah[a]);
                }
#pragma unroll
                for (int bb = 0; bb < 2; ++bb)
                    ldsm4(bmat_addr(whb, cq * 32 + bb * 16, ks * 16, lane), bh[bb]);
#pragma unroll
                for (int a = 0; a < 2; ++a)
#pragma unroll
                    for (int bb = 0; bb < 2; ++bb) {
                        mma_fp(acc[a][bb * 2],     ah[a], bh[bb][0], bh[bb][2]);
                        mma_fp(acc[a][bb * 2 + 1], ah[a], bh[bb][1], bh[bb][3]);
                    }
            }
        }
        __syncthreads();   // both buffers free

        // cp W_proj half 0 into buf1 (overlaps squash)
        {
            const uint32_t* pH = g_wp_f16 + (size_t)(e * 2 + 0) * 4096;
#pragma unroll
            for (int k = 0; k < 4; ++k) {
                int i = tid + k * 256;
                cp16s(sb + WOFF + 16384 + i * 16, pH + i * 4);
            }
            CP_COMMIT();
        }

        // ---- bias + per-pixel sum of squares (4 co-quarters) ----
#pragma unroll
        for (int a = 0; a < 2; ++a) {
            float sa = 0.f, sb2 = 0.f;
#pragma unroll
            for (int nn = 0; nn < 4; ++nn) {
                int co = cq * 32 + nn * 8 + t4 * 2;
                float bc0 = __ldg(&bc_all[e * CC + co]);
                float bc1 = __ldg(&bc_all[e * CC + co + 1]);
                acc[a][nn][0] += bc0; acc[a][nn][1] += bc1;
                acc[a][nn][2] += bc0; acc[a][nn][3] += bc1;
                sa = fmaf(acc[a][nn][0], acc[a][nn][0], sa);
                sa = fmaf(acc[a][nn][1], acc[a][nn][1], sa);
                sb2 = fmaf(acc[a][nn][2], acc[a][nn][2], sb2);
                sb2 = fmaf(acc[a][nn][3], acc[a][nn][3], sb2);
            }
            sa += __shfl_xor_sync(0xffffffffu, sa, 1);
            sa += __shfl_xor_sync(0xffffffffu, sa, 2);
            sb2 += __shfl_xor_sync(0xffffffffu, sb2, 1);
            sb2 += __shfl_xor_sync(0xffffffffu, sb2, 2);
            if (t4 == 0) {
                int pxa = ph * 32 + a * 16 + gq;
                spart[cq * 64 + pxa] = sa;
                spart[cq * 64 + pxa + 8] = sb2;
            }
        }
        __syncthreads();
        if (tid < 64) {
            float sn = spart[tid] + spart[64 + tid] + spart[128 + tid] + spart[192 + tid];
            ssc[tid] = sn / (1.f + sn) / (sqrtf(sn) + 1e-8f);
        }
        __syncthreads();

        // ---- scale + stage u into buf0 (64 px rows x 256B, swizzled) ----
#pragma unroll
        for (int a = 0; a < 2; ++a) {
            int pxa = ph * 32 + a * 16 + gq;
            float s0 = ssc[pxa], s1 = ssc[pxa + 8];
#pragma unroll
            for (int nn = 0; nn < 4; ++nn) {
                int cb = (cq * 32 + nn * 8 + t4 * 2) * 2;
                uint32_t w0 = packh2(acc[a][nn][0] * s0, acc[a][nn][1] * s0);
                uint32_t o0 = pxa * 256 + (cb ^ ((pxa & 7) << 4));
                *(uint32_t*)(smem + WOFF + o0) = w0;
                uint32_t w1 = packh2(acc[a][nn][2] * s1, acc[a][nn][3] * s1);
                int px2 = pxa + 8;
                uint32_t o1 = px2 * 256 + (cb ^ ((px2 & 7) << 4));
                *(uint32_t*)(smem + WOFF + o1) = w1;
            }
        }
        CP_WAIT0();
        __syncthreads();

        // ---- GEMM2: K=128 in 2 ci-half passes (u buf0, Wp half buf1) ----
#pragma unroll
        for (int a = 0; a < 2; ++a)
#pragma unroll
            for (int nn = 0; nn < 4; ++nn)
#pragma unroll
                for (int i = 0; i < 4; ++i) acc[a][nn][i] = 0.f;

        for (int h2 = 0; h2 < 2; ++h2) {
#pragma unroll
            for (int ks = 0; ks < 4; ++ks) {
                uint32_t ah[2][4], bh[2][4];
#pragma unroll
                for (int a = 0; a < 2; ++a)
                    ldsm4(amat_addr(sb + WOFF, ph * 32 + a * 16, h2 * 64 + ks * 16, lane), ah[a]);
#pragma unroll
                for (int bb = 0; bb < 2; ++bb)
                    ldsm4(bmat_addr(sb + WOFF + 16384, cq * 32 + bb * 16, ks * 16, lane), bh[bb]);
#pragma unroll
                for (int a = 0; a < 2; ++a)
#pragma unroll
                    for (int bb = 0; bb < 2; ++bb) {
                        mma_fp(acc[a][bb * 2],     ah[a], bh[bb][0], bh[bb][2]);
                        mma_fp(acc[a][bb * 2 + 1], ah[a], bh[bb][1], bh[bb][3]);
                    }
            }
            if (h2 == 0) {
                __syncthreads();    // all warps done reading buf1 (half 0)
                const uint32_t* pH = g_wp_f16 + (size_t)(e * 2 + 1) * 4096;
#pragma unroll
                for (int k = 0; k < 4; ++k) {
                    int i = tid + k * 256;
                    cp16s(sb + WOFF + 16384 + i * 16, pH + i * 4);
                }
                CP_COMMIT();
                CP_WAIT0();
                __syncthreads();
            }
        }
        __syncthreads();   // done reading bufs; region reusable for staging

        // ---- v = acc + bp -> staging [128co][64px] -> scratch ----
        float* stg = (float*)(smem + WOFF);
#pragma unroll
        for (int a = 0; a < 2; ++a) {
            int pxa = ph * 32 + a * 16 + gq;
#pragma unroll
            for (int nn = 0; nn < 4; ++nn) {
                int cl = cq * 32 + nn * 8 + t4 * 2;
                float bp0 = __ldg(&bp_all[e * CC + cl]);
                float bp1 = __ldg(&bp_all[e * CC + cl + 1]);
                stg[cl * 64 + pxa]           = acc[a][nn][0] + bp0;
                stg[(cl + 1) * 64 + pxa]     = acc[a][nn][1] + bp1;
                stg[cl * 64 + pxa + 8]       = acc[a][nn][2] + bp0;
                stg[(cl + 1) * 64 + pxa + 8] = acc[a][nn][3] + bp1;
            }
        }
        __syncthreads();
        {
            float* dst = g_scr + (size_t)(e * NBLK + blk) * 8192;
#pragma unroll
            for (int k = 0; k < 8; ++k) {
                int i = tid + k * 256;
                int cl = i >> 4, p4 = (i & 15) * 4;
                float4 v = *(float4*)&stg[cl * 64 + p4];
                *(float4*)&dst[cl * 64 + p4] = v;
            }
        }
        __syncthreads();
    }

    // ---- combine: y_g = sum_e w_ge * v_e ----
    __syncthreads();
#pragma unroll 1
    for (int k = 0; k < 8; ++k) {
        int i = tid + k * 256;                 // 0..2047 float4 ids
        int co = i >> 4, p4 = (i & 15) * 4;
        float4 y0 = {0, 0, 0, 0}, y1 = y0, y2 = y0, y3 = y0;
#pragma unroll
        for (int e = 0; e < EE; ++e) {
            float a0 = swg[e], a1 = swg[8 + e], a2 = swg[16 + e], a3 = swg[24 + e];
            if (a0 == 0.f && a1 == 0.f && a2 == 0.f && a3 == 0.f) continue;
            float4 v = *(const float4*)(g_scr + (size_t)(e * NBLK + blk) * 8192 + co * 64 + p4);
            y0.x += a0 * v.x; y0.y += a0 * v.y; y0.z += a0 * v.z; y0.w += a0 * v.w;
            y1.x += a1 * v.x; y1.y += a1 * v.y; y1.z += a1 * v.z; y1.w += a1 * v.w;
            y2.x += a2 * v.x; y2.y += a2 * v.y; y2.z += a2 * v.z; y2.w += a2 * v.w;
            y3.x += a3 * v.x; y3.y += a3 * v.y; y3.z += a3 * v.z; y3.w += a3 * v.w;
        }
        size_t gidx = (size_t)b * IMG + (size_t)co * HWPIX + (size_t)row * 64 + p4;
        *(float4*)(out + gidx) = y0;
        *(float4*)(out + YSZ + gidx) = y1;
        *(float4*)(out + 2 * YSZ + gidx) = y2;
        *(float4*)(out + 3 * YSZ + gidx) = y3;
    }
}

// ---------------------------------------------------------------------------
extern "C" void kernel_launch(void* const* d_in, const int* in_sizes, int n_in,
                              void* d_out, int out_size) {
    const float* x  = (const float*)d_in[0];
    const float* g1 = (const float*)d_in[1];
    const float* g2 = (const float*)d_in[2];
    const float* g3 = (const float*)d_in[3];
    const float* g4 = (const float*)d_in[4];
    const float* Wc = (const float*)d_in[5];
    const float* bc = (const float*)d_in[6];
    const float* Wp = (const float*)d_in[7];
    const float* bp = (const float*)d_in[8];
    float* out = (float*)d_out;

    cudaFuncSetAttribute(moe_main, cudaFuncAttributeMaxDynamicSharedMemorySize, SMEM_BYTES);

    mean_kernel<<<BB * CC, 256>>>(x);
    gate_kernel<<<1, 32>>>(g1, g2, g3, g4, out + (out_size - 1));
    prep_all<<<EE * 18 + EE * 2, 256>>>(Wc, Wp);
    moe_main<<<NBLK, 256, SMEM_BYTES>>>(x, bc, bp, out);   // launch #4 -> ncu target
}